// round 4
// baseline (speedup 1.0000x reference)
#include <cuda_runtime.h>
#include <stdint.h>

#define C_     128
#define HH     112
#define WW     112
#define BATCH  8
#define TAPS   9
#define TABW   512            // 511 valid entries + 1 pad
#define RCH    16             // output rows per work item
#define NCHUNK 7              // 112 / 16
#define ITEMS  (BATCH * C_ * NCHUNK)   // 7168
#define TRI    (RCH + 2)      // 18 staged tile rows
#define TCU    114            // used tile cols (112 + 2 halo)
#define TCW    116            // padded u16 stride
#define STRIPS 28             // 4-col strips
#define BANDS  8              // row bands (2 rows each)
#define BROWS  2
#define NTHR   (STRIPS * BANDS)   // 224
#define NBLK   1184           // 148 SMs * 8 blocks
#define QBASE  (ITEMS / NBLK) // 6
#define QREM   (ITEMS - QBASE * NBLK)  // 64

// Per-channel, per-tap folded LUT: T[c][tap][t2+255] = lut[|t1|,|t2|]*sign/1000
__device__ float g_table[C_ * TAPS * TABW];

__global__ void build_table_kernel(const float* __restrict__ weight,
                                   const float* __restrict__ lut) {
    int ct  = blockIdx.x;            // (c, tap)
    float w  = weight[ct];
    float t1 = rintf(w * 1000.0f);
    t1 = fminf(fmaxf(t1, -255.0f), 255.0f);
    int   i1 = (int)fabsf(t1);
    float s1 = (t1 > 0.0f) ? 1.0f : ((t1 < 0.0f) ? -1.0f : 0.0f);

    float* dst = g_table + (size_t)ct * TABW;
    const float* lrow = lut + i1 * 256;
    for (int j = threadIdx.x; j < TABW; j += blockDim.x) {
        float v = 0.0f;
        if (j < 511) {
            int t2 = j - 255;
            int i2 = abs(t2);
            bool pos = (s1 > 0.0f && t2 > 0) || (s1 < 0.0f && t2 < 0);
            v = lrow[i2] * (pos ? 1.0f : -1.0f) * (1.0f / 1000.0f);
        }
        dst[j] = v;
    }
}

// Accumulate one tap-row (dr) into 4 horizontal outputs from 3 packed idx words.
__device__ __forceinline__ void row_accum(const float* __restrict__ tab, int dr,
                                          uint32_t w0, uint32_t w1, uint32_t w2,
                                          float& o0, float& o1, float& o2, float& o3) {
    int i0 = (int)(w0 & 0xffffu), i1 = (int)(w0 >> 16);
    int i2 = (int)(w1 & 0xffffu), i3 = (int)(w1 >> 16);
    int i4 = (int)(w2 & 0xffffu), i5 = (int)(w2 >> 16);
    const float* t0 = tab + (dr * 3 + 0) * TABW;
    const float* t1 = tab + (dr * 3 + 1) * TABW;
    const float* t2 = tab + (dr * 3 + 2) * TABW;
    o0 += t0[i0] + t1[i1] + t2[i2];
    o1 += t0[i1] + t1[i2] + t2[i3];
    o2 += t0[i2] + t1[i3] + t2[i4];
    o3 += t0[i3] + t1[i4] + t2[i5];
}

__global__ __launch_bounds__(NTHR, 8) void conv_kernel(const float* __restrict__ x,
                                                       float* __restrict__ out) {
    __shared__ float    tab[TAPS * TABW];        // 18432 B
    __shared__ uint16_t sidx[TRI * TCW];         // 4176 B

    int k     = blockIdx.x;
    int t     = threadIdx.x;
    int start = k * QBASE + min(k, QREM);
    int nit   = QBASE + (k < QREM ? 1 : 0);
    int cprev = -1;

    for (int it = start; it < start + nit; it++) {
        int c     = it / (BATCH * NCHUNK);          // c-major ordering
        int rem   = it - c * (BATCH * NCHUNK);
        int b     = rem / NCHUNK;
        int chunk = rem - b * NCHUNK;
        int r0    = chunk * RCH;

        // Stage the folded table only when the channel changes.
        if (c != cprev) {
            const float4* ts4 = (const float4*)(g_table + (size_t)c * TAPS * TABW);
            float4* td4 = (float4*)tab;
            #pragma unroll
            for (int i = t; i < (TAPS * TABW) / 4; i += NTHR)
                td4[i] = ts4[i];
            cprev = c;
        }

        // Stage idx tile (quantize each pixel once to table index [0,510]).
        const float* xp = x + ((size_t)(b * C_ + c)) * (HH * WW);
        for (int e = t; e < TRI * TCU; e += NTHR) {
            int tr = e / TCU;
            int tc = e - tr * TCU;
            int gr = r0 - 1 + tr;
            int gc = tc - 1;
            float v = 0.0f;                    // zero-pad -> idx 255
            if (gr >= 0 && gr < HH && gc >= 0 && gc < WW)
                v = xp[gr * WW + gc];
            float q = fminf(fmaxf(rintf(v), -255.0f), 255.0f);
            sidx[tr * TCW + tc] = (uint16_t)((int)q + 255);
        }
        __syncthreads();

        // Thread = one 4-col strip in one 2-row band. Rolling packed idx regs.
        int s    = t % STRIPS;
        int band = t / STRIPS;
        int col0 = 4 * s;
        int rb   = band * BROWS;

        const uint32_t* sidx32 = (const uint32_t*)sidx;
        const int RW = TCW / 2;                // 58 u32 per tile row
        int base = rb * RW + 2 * s;

        uint32_t a0 = sidx32[base + 0], a1 = sidx32[base + 1], a2 = sidx32[base + 2];
        base += RW;
        uint32_t b0 = sidx32[base + 0], b1 = sidx32[base + 1], b2 = sidx32[base + 2];

        float* op = out + ((size_t)(b * C_ + c)) * (HH * WW) + (r0 + rb) * WW + col0;

        #pragma unroll
        for (int i = 0; i < BROWS; i++) {
            base += RW;
            uint32_t c0 = sidx32[base + 0], c1 = sidx32[base + 1], c2 = sidx32[base + 2];

            float o0 = 0.0f, o1 = 0.0f, o2 = 0.0f, o3 = 0.0f;
            row_accum(tab, 0, a0, a1, a2, o0, o1, o2, o3);
            row_accum(tab, 1, b0, b1, b2, o0, o1, o2, o3);
            row_accum(tab, 2, c0, c1, c2, o0, o1, o2, o3);

            *(float4*)op = make_float4(o0, o1, o2, o3);
            op += WW;

            a0 = b0; a1 = b1; a2 = b2;
            b0 = c0; b1 = c1; b2 = c2;
        }
        __syncthreads();   // guard sidx/tab overwrite by next item
    }
}

extern "C" void kernel_launch(void* const* d_in, const int* in_sizes, int n_in,
                              void* d_out, int out_size) {
    const float* x      = (const float*)d_in[0];
    const float* weight = (const float*)d_in[1];
    const float* lut    = (const float*)d_in[2];
    float* out          = (float*)d_out;

    build_table_kernel<<<C_ * TAPS, 128>>>(weight, lut);
    conv_kernel<<<NBLK, NTHR>>>(x, out);
}

// round 5
// speedup vs baseline: 1.0633x; 1.0633x over previous
#include <cuda_runtime.h>
#include <stdint.h>

#define C_     128
#define HH     112
#define WW     112
#define BATCH  8
#define TAPS   9
#define TABW   512            // 511 valid entries + 1 pad
#define SROWS  56             // output rows per stripe
#define TRI    (SROWS + 2)    // 58 staged tile rows
#define TCU    114            // used tile cols (112 + 2 halo)
#define TCW    116            // padded u16 stride (232 B)
#define STRIPS 28             // 4-col strips
#define BANDS  8              // row bands per stripe
#define BROWS  7              // rows per band (8*7 = 56)
#define NTHR   (STRIPS * BANDS)   // 224

// Per-channel, per-tap folded LUT: T[c][tap][t2+255] = lut[|t1|,|t2|]*sign/1000
__device__ float g_table[C_ * TAPS * TABW];

__global__ void build_table_kernel(const float* __restrict__ weight,
                                   const float* __restrict__ lut) {
    int ct  = blockIdx.x;            // (c, tap)
    float w  = weight[ct];
    float t1 = rintf(w * 1000.0f);
    t1 = fminf(fmaxf(t1, -255.0f), 255.0f);
    int   i1 = (int)fabsf(t1);
    float s1 = (t1 > 0.0f) ? 1.0f : ((t1 < 0.0f) ? -1.0f : 0.0f);

    int j = threadIdx.x;             // 512 threads, one entry each
    float v = 0.0f;
    if (j < 511) {
        int t2 = j - 255;
        int i2 = abs(t2);
        bool pos = (s1 > 0.0f && t2 > 0) || (s1 < 0.0f && t2 < 0);
        v = lut[i1 * 256 + i2] * (pos ? 1.0f : -1.0f) * (1.0f / 1000.0f);
    }
    g_table[(size_t)ct * TABW + j] = v;
}

// Accumulate one tap-row (dr) into 4 horizontal outputs from 3 packed idx words.
__device__ __forceinline__ void row_accum(const float* __restrict__ tab, int dr,
                                          uint32_t w0, uint32_t w1, uint32_t w2,
                                          float& o0, float& o1, float& o2, float& o3) {
    int i0 = (int)(w0 & 0xffffu), i1 = (int)(w0 >> 16);
    int i2 = (int)(w1 & 0xffffu), i3 = (int)(w1 >> 16);
    int i4 = (int)(w2 & 0xffffu), i5 = (int)(w2 >> 16);
    const float* t0 = tab + (dr * 3 + 0) * TABW;
    const float* t1 = tab + (dr * 3 + 1) * TABW;
    const float* t2 = tab + (dr * 3 + 2) * TABW;
    o0 += t0[i0] + t1[i1] + t2[i2];
    o1 += t0[i1] + t1[i2] + t2[i3];
    o2 += t0[i2] + t1[i3] + t2[i4];
    o3 += t0[i3] + t1[i4] + t2[i5];
}

__global__ __launch_bounds__(NTHR, 7) void conv_kernel(const float* __restrict__ x,
                                                       float* __restrict__ out) {
    __shared__ float    tab[TAPS * TABW];        // 18432 B
    __shared__ uint16_t sidx[TRI * TCW];         // 13456 B  (total 31888 B -> 7 blocks/SM)

    int bid = blockIdx.x;                  // (b, c)
    int c   = bid & (C_ - 1);
    int b   = bid >> 7;
    int t   = threadIdx.x;

    // Stage this channel's folded table once (float4 copies).
    {
        const float4* ts4 = (const float4*)(g_table + (size_t)c * TAPS * TABW);
        float4* td4 = (float4*)tab;
        #pragma unroll
        for (int i = t; i < (TAPS * TABW) / 4; i += NTHR)
            td4[i] = ts4[i];
    }

    const float* xp = x + ((size_t)(b * C_ + c)) * (HH * WW);
    float* obase    = out + ((size_t)(b * C_ + c)) * (HH * WW);

    int s    = t % STRIPS;                 // col strip
    int band = t / STRIPS;                 // row band
    int col0 = 4 * s;

    #pragma unroll
    for (int stripe = 0; stripe < 2; stripe++) {
        int r0 = stripe * SROWS;

        // Stage idx tile (quantize each pixel once to table index [0,510]).
        for (int e = t; e < TRI * TCU; e += NTHR) {
            int tr = e / TCU;
            int tc = e - tr * TCU;
            int gr = r0 - 1 + tr;
            int gc = tc - 1;
            float v = 0.0f;                    // zero-pad -> idx 255
            if (gr >= 0 && gr < HH && gc >= 0 && gc < WW)
                v = xp[gr * WW + gc];
            float q = fminf(fmaxf(rintf(v), -255.0f), 255.0f);
            sidx[tr * TCW + tc] = (uint16_t)((int)q + 255);
        }
        __syncthreads();

        // Thread = one 4-col strip in one 7-row band. Rolling packed idx regs.
        int rb = band * BROWS;

        const uint32_t* sidx32 = (const uint32_t*)sidx;
        const int RW = TCW / 2;                // 58 u32 per tile row
        int base = rb * RW + 2 * s;

        uint32_t a0 = sidx32[base + 0], a1 = sidx32[base + 1], a2 = sidx32[base + 2];
        base += RW;
        uint32_t b0 = sidx32[base + 0], b1 = sidx32[base + 1], b2 = sidx32[base + 2];

        float* op = obase + (r0 + rb) * WW + col0;

        #pragma unroll
        for (int i = 0; i < BROWS; i++) {
            base += RW;
            uint32_t c0 = sidx32[base + 0], c1 = sidx32[base + 1], c2 = sidx32[base + 2];

            float o0 = 0.0f, o1 = 0.0f, o2 = 0.0f, o3 = 0.0f;
            row_accum(tab, 0, a0, a1, a2, o0, o1, o2, o3);
            row_accum(tab, 1, b0, b1, b2, o0, o1, o2, o3);
            row_accum(tab, 2, c0, c1, c2, o0, o1, o2, o3);

            *(float4*)op = make_float4(o0, o1, o2, o3);
            op += WW;

            a0 = b0; a1 = b1; a2 = b2;
            b0 = c0; b1 = c1; b2 = c2;
        }
        __syncthreads();   // protect sidx before next stripe overwrites it
    }
}

extern "C" void kernel_launch(void* const* d_in, const int* in_sizes, int n_in,
                              void* d_out, int out_size) {
    const float* x      = (const float*)d_in[0];
    const float* weight = (const float*)d_in[1];
    const float* lut    = (const float*)d_in[2];
    float* out          = (float*)d_out;

    build_table_kernel<<<C_ * TAPS, TABW>>>(weight, lut);
    conv_kernel<<<BATCH * C_, NTHR>>>(x, out);
}